// round 14
// baseline (speedup 1.0000x reference)
#include <cuda_runtime.h>
#include <cuda_bf16.h>
#include <cstdint>

// Problem constants
#define BB   2048
#define NAG  8
#define ACT  16
#define HIDN 64
#define GRID_MMA 444   // 3 CTAs per SM (148 SMs)

// Scratch (__device__ globals: allowed)
__device__ float g_w1aT[HIDN * 128];   // w1aT[k*128 + row] = W1[(g*48+32+a)*64 + k]
__device__ float g_sbase[BB * HIDN];   // sbase[b][n] = base+tot+b1  (512 KB)
__device__ int   g_sidx[BB * NAG];     // one-hot indices (64 KB)

// ---------------------------------------------------------------------------
__device__ __forceinline__ uint32_t pack_hi(float a, float b) {
    uint32_t r;
    asm("prmt.b32 %0, %1, %2, 0x7632;" : "=r"(r)
        : "r"(__float_as_uint(a)), "r"(__float_as_uint(b)));
    return r;
}
__device__ __forceinline__ uint32_t pack_lo(float a, float b) {
    float ha = __uint_as_float(__float_as_uint(a) & 0xffff0000u);
    float hb = __uint_as_float(__float_as_uint(b) & 0xffff0000u);
    float la = a - ha, lb = b - hb;
    uint32_t r;
    asm("cvt.rn.bf16x2.f32 %0, %1, %2;" : "=r"(r) : "f"(lb), "f"(la));
    return r;
}
__device__ __forceinline__ uint32_t smem_u32(const void* p) {
    uint32_t a;
    asm("{ .reg .u64 t; cvta.to.shared.u64 t, %1; cvt.u32.u64 %0, t; }" : "=r"(a) : "l"(p));
    return a;
}
__device__ __forceinline__ void fma4(float4& acc, float s, const float4 w) {
    acc.x = fmaf(s, w.x, acc.x);
    acc.y = fmaf(s, w.y, acc.y);
    acc.z = fmaf(s, w.z, acc.z);
    acc.w = fmaf(s, w.w, acc.w);
}

#define LDSM_X4(r, addr) \
    asm volatile("ldmatrix.sync.aligned.m8n8.x4.shared.b16 {%0,%1,%2,%3}, [%4];" \
        : "=r"((r)[0]), "=r"((r)[1]), "=r"((r)[2]), "=r"((r)[3]) : "r"(addr))
#define LDSM_X4_T(r, addr) \
    asm volatile("ldmatrix.sync.aligned.m8n8.x4.trans.shared.b16 {%0,%1,%2,%3}, [%4];" \
        : "=r"((r)[0]), "=r"((r)[1]), "=r"((r)[2]), "=r"((r)[3]) : "r"(addr))
#define MMA16816(c, a, b0, b1) \
    asm volatile("mma.sync.aligned.m16n8k16.row.col.f32.bf16.bf16.f32 " \
        "{%0,%1,%2,%3}, {%4,%5,%6,%7}, {%8,%9}, {%0,%1,%2,%3};" \
        : "+f"((c)[0]), "+f"((c)[1]), "+f"((c)[2]), "+f"((c)[3]) \
        : "r"((a)[0]), "r"((a)[1]), "r"((a)[2]), "r"((a)[3]), "r"(b0), "r"(b1))
#define CP_ASYNC16(dst, src) \
    asm volatile("cp.async.cg.shared.global [%0], [%1], 16;" :: "r"(dst), "l"(src) : "memory")
#define CP_COMMIT() asm volatile("cp.async.commit_group;" ::: "memory")
#define CP_WAIT0()  asm volatile("cp.async.wait_group 0;" ::: "memory")

// ---------------------------------------------------------------------------
// Kernel 1 (prep2): compact layer-1 base. R8 structure, 8x smaller output.
// 256 CTAs x 256 thr, 8 batches/CTA, thread = (kq in 2, bl in 8, nq in 16).
// Writes g_sbase[b][64] = base + b1 + sum_g w1row(g, idx_g), g_sidx[b][8].
// ---------------------------------------------------------------------------
__global__ void __launch_bounds__(256) prep2_kernel(
    const float* __restrict__ hidden,   // [B, 8, 32]
    const float* __restrict__ actions,  // [B, 8, 16]
    const float* __restrict__ w1,       // [384, 64]
    const float* __restrict__ b1)       // [64]
{
    __shared__ float  sh[8 * 256];
    __shared__ float4 spart[8][16];
    __shared__ int    sidx[64];

    const int tid = threadIdx.x;
    const int b0  = blockIdx.x * 8;
    const float4* __restrict__ w1v = reinterpret_cast<const float4*>(w1);

    if (blockIdx.x == 0) {
        for (int e = tid; e < HIDN * 128; e += 256) {
            const int k   = e >> 7;
            const int row = e & 127;
            const int g   = row >> 4;
            const int a   = row & 15;
            g_w1aT[e] = __ldg(w1 + (g * 48 + 32 + a) * 64 + k);
        }
    }

    {
        const float4* hv = reinterpret_cast<const float4*>(hidden + (size_t)b0 * 256);
        float4* shv = reinterpret_cast<float4*>(sh);
        #pragma unroll
        for (int e = tid; e < 512; e += 256) shv[e] = __ldg(hv + e);
    }

    if (tid < 64) {
        const int bl = tid >> 3, g = tid & 7;
        const float* ag = actions + (size_t)(b0 + bl) * 128 + g * 16;
        float s = 0.f;
        #pragma unroll
        for (int a = 0; a < ACT; ++a) s = fmaf(__ldg(ag + a), (float)a, s);
        const int iv = __float2int_rn(s);
        sidx[tid] = iv;
        g_sidx[(b0 + bl) * NAG + g] = iv;
    }
    __syncthreads();

    const int kq = tid >> 7;
    const int bl = (tid >> 4) & 7;
    const int nq = tid & 15;

    float4 acc = make_float4(0.f, 0.f, 0.f, 0.f);
    const float* h0 = sh + bl * 256 + kq * 128;
    #pragma unroll
    for (int j2 = 0; j2 < 4; ++j2) {
        const int j = kq * 4 + j2;
        #pragma unroll
        for (int i4 = 0; i4 < 8; ++i4) {
            const int wrow = j * 48 + i4 * 4;
            const float4 w0  = __ldg(w1v + (wrow + 0) * 16 + nq);
            const float4 w1_ = __ldg(w1v + (wrow + 1) * 16 + nq);
            const float4 w2_ = __ldg(w1v + (wrow + 2) * 16 + nq);
            const float4 w3_ = __ldg(w1v + (wrow + 3) * 16 + nq);
            const float4 h = *reinterpret_cast<const float4*>(h0 + j2 * 32 + i4 * 4);
            fma4(acc, h.x, w0); fma4(acc, h.y, w1_);
            fma4(acc, h.z, w2_); fma4(acc, h.w, w3_);
        }
    }
    if (kq == 1) spart[bl][nq] = acc;
    __syncthreads();

    if (kq == 0) {
        const float4 b1v = __ldg(reinterpret_cast<const float4*>(b1) + nq);
        const float4 p = spart[bl][nq];
        float4 base;
        base.x = acc.x + p.x + b1v.x;
        base.y = acc.y + p.y + b1v.y;
        base.z = acc.z + p.z + b1v.z;
        base.w = acc.w + p.w + b1v.w;

        #pragma unroll
        for (int g = 0; g < NAG; ++g) {
            const float4 av = __ldg(w1v + (g * 48 + 32 + sidx[bl * 8 + g]) * 16 + nq);
            base.x += av.x; base.y += av.y; base.z += av.z; base.w += av.w;
        }
        *reinterpret_cast<float4*>(&g_sbase[(size_t)(b0 + bl) * HIDN + nq * 4]) = base;
    }
}

// ---------------------------------------------------------------------------
// Kernel 2: persistent HMMA GEMM (R9 structure, measured best) with 288-byte
// sbase/sidx slabs instead of 2KB u slabs. Build phase:
//   x1[row,k] = relu(sbase[k] + w1aT[k,row] - w1aT[k,rowsub(g)])
// (w1aT is 32KB and L1-resident now that SMEM/CTA is only ~50KB.)
// ---------------------------------------------------------------------------
#define SM_A     0        // 32768
#define SM_B     32768    // 16384: rows 0-63 = W_hi, 64-127 = W_lo
#define SM_B2    49152
#define SM_W3    49408
#define SM_SLAB  49664    // 2 x 512 (sbase 256B at +0, sidx 32B at +256)
#define SMEM_SZ  50688

__global__ void __launch_bounds__(128, 3) mma_kernel(
    const float* __restrict__ w2,   // [64, 64] (k-major)
    const float* __restrict__ b2,   // [64]
    const float* __restrict__ w3,   // [64]
    const float* __restrict__ b3,   // [1]
    float* __restrict__ out)        // [B, 128]
{
    extern __shared__ __align__(16) char dsm[];
    const uint32_t smAddr = smem_u32(dsm);
    const uint32_t smA    = smAddr + SM_A;
    const uint32_t smB    = smAddr + SM_B;
    const uint32_t smSlab = smAddr + SM_SLAB;
    float* sb2 = reinterpret_cast<float*>(dsm + SM_B2);
    float* sw3 = reinterpret_cast<float*>(dsm + SM_W3);

    const int tid  = threadIdx.x;
    const int w    = tid >> 5;
    const int lane = tid & 31;

    if (tid < 64) {
        sb2[tid] = __ldg(b2 + tid);
        sw3[tid] = __ldg(w3 + tid);
    }
    const float b3v = __ldg(b3);

    // prologue: prefetch slab for first tile into buffer 0
    if (tid < 16)
        CP_ASYNC16(smSlab + tid * 16, g_sbase + (size_t)blockIdx.x * 64 + tid * 4);
    else if (tid < 18)
        CP_ASYNC16(smSlab + 256 + (tid - 16) * 16,
                   g_sidx + (size_t)blockIdx.x * 8 + (tid - 16) * 4);
    CP_COMMIT();

    // build B = [W_hi; W_lo] (128 k-rows x 64 n), xor-swizzled
    for (int e = tid; e < 128 * 32; e += 128) {
        const int kk = e >> 5;
        const int nw = e & 31;
        const int k  = kk & 63;
        const float2 f = __ldg(reinterpret_cast<const float2*>(w2 + k * 64 + 2 * nw));
        const uint32_t word = (kk < 64) ? pack_hi(f.x, f.y) : pack_lo(f.x, f.y);
        const int nc = nw >> 2;
        const uint32_t byte = (uint32_t)kk * 128u + (uint32_t)((nc ^ (kk & 7)) << 4)
                            + (uint32_t)((nw & 3) << 2);
        *reinterpret_cast<uint32_t*>(dsm + SM_B + byte) = word;
    }

    // per-lane ldmatrix address precompute
    const int g2  = lane >> 4;
    const int gh  = (lane >> 3) & 1;
    const int lr  = lane & 7;
    const int grp = lane >> 2;
    const int tig = lane & 3;

    uint32_t aBase[2];
    #pragma unroll
    for (int mt = 0; mt < 2; ++mt)
        aBase[mt] = smA + (uint32_t)(32 * w + 16 * mt + 8 * gh + lr) * 256u;

    const int nadd = lane >> 4;
    const uint32_t bBase = smB + (uint32_t)(8 * ((lane >> 3) & 1) + lr) * 128u;
    uint32_t nxor[4];
    #pragma unroll
    for (int np = 0; np < 4; ++np)
        nxor[np] = (uint32_t)(((2 * np + nadd) ^ lr) << 4);

    const int row = tid;
    const int gq  = row >> 4;
    const uint32_t rbase = (uint32_t)row * 256u;
    const int rx  = row & 7;

    int it = 0;
    for (int b = blockIdx.x; b < BB; b += GRID_MMA) {
        const int cur = it & 1;

        CP_WAIT0();
        __syncthreads();

        const float4* sbase4 = reinterpret_cast<const float4*>(dsm + SM_SLAB + cur * 512);
        const int*    sidx_s = reinterpret_cast<const int*>(dsm + SM_SLAB + cur * 512 + 256);
        const int rowsub = gq * 16 + sidx_s[gq];

        // build A': x1[row,k] = relu(sbase[k] + w1aT[k,row] - w1aT[k,rowsub])
        #pragma unroll
        for (int c8 = 0; c8 < 8; ++c8) {
            const int k0 = c8 * 8;
            const float4 s0 = sbase4[c8 * 2];
            const float4 s1 = sbase4[c8 * 2 + 1];
            float x[8];
            x[0] = s0.x; x[1] = s0.y; x[2] = s0.z; x[3] = s0.w;
            x[4] = s1.x; x[5] = s1.y; x[6] = s1.z; x[7] = s1.w;
            #pragma unroll
            for (int j = 0; j < 8; ++j) {
                const int k = k0 + j;
                x[j] = fmaxf(x[j] + __ldg(g_w1aT + k * 128 + row)
                                  - __ldg(g_w1aT + k * 128 + rowsub), 0.f);
            }

            uint4 hi4, lo4;
            hi4.x = pack_hi(x[0], x[1]); hi4.y = pack_hi(x[2], x[3]);
            hi4.z = pack_hi(x[4], x[5]); hi4.w = pack_hi(x[6], x[7]);
            lo4.x = pack_lo(x[0], x[1]); lo4.y = pack_lo(x[2], x[3]);
            lo4.z = pack_lo(x[4], x[5]); lo4.w = pack_lo(x[6], x[7]);

            *reinterpret_cast<uint4*>(dsm + SM_A + rbase + ((c8 ^ rx) << 4))       = hi4;
            *reinterpret_cast<uint4*>(dsm + SM_A + rbase + (((8 + c8) ^ rx) << 4)) = lo4;
        }

        // prefetch slab for the next tile
        {
            int bn = b + GRID_MMA;
            if (bn >= BB) bn = b;
            if (tid < 16)
                CP_ASYNC16(smSlab + (cur ^ 1) * 512 + tid * 16,
                           g_sbase + (size_t)bn * 64 + tid * 4);
            else if (tid < 18)
                CP_ASYNC16(smSlab + (cur ^ 1) * 512 + 256 + (tid - 16) * 16,
                           g_sidx + (size_t)bn * 8 + (tid - 16) * 4);
            CP_COMMIT();
        }
        __syncthreads();

        // mma phase: 4 physical k-chunks x 3 split products (R9, measured best)
        float acc[2][8][4];
        #pragma unroll
        for (int mt = 0; mt < 2; ++mt)
            #pragma unroll
            for (int nt = 0; nt < 8; ++nt)
                #pragma unroll
                for (int q = 0; q < 4; ++q) acc[mt][nt][q] = 0.f;

        #pragma unroll
        for (int kp = 0; kp < 4; ++kp) {
            uint32_t ah[2][4], al[2][4];
            #pragma unroll
            for (int mt = 0; mt < 2; ++mt) {
                LDSM_X4(ah[mt], aBase[mt] + (uint32_t)(((2 * kp + g2) ^ lr) << 4));
                LDSM_X4(al[mt], aBase[mt] + (uint32_t)(((8 + 2 * kp + g2) ^ lr) << 4));
            }
            uint32_t bh[4][4], blo[4][4];
            #pragma unroll
            for (int np = 0; np < 4; ++np) {
                LDSM_X4_T(bh[np],  bBase + (uint32_t)(kp * 2048)       + nxor[np]);
                LDSM_X4_T(blo[np], bBase + (uint32_t)((4 + kp) * 2048) + nxor[np]);
            }
            #pragma unroll
            for (int mt = 0; mt < 2; ++mt) {
                #pragma unroll
                for (int np = 0; np < 4; ++np) {
                    MMA16816(acc[mt][2 * np + 0], ah[mt], bh[np][0],  bh[np][1]);
                    MMA16816(acc[mt][2 * np + 1], ah[mt], bh[np][2],  bh[np][3]);
                    MMA16816(acc[mt][2 * np + 0], al[mt], bh[np][0],  bh[np][1]);
                    MMA16816(acc[mt][2 * np + 1], al[mt], bh[np][2],  bh[np][3]);
                    MMA16816(acc[mt][2 * np + 0], ah[mt], blo[np][0], blo[np][1]);
                    MMA16816(acc[mt][2 * np + 1], ah[mt], blo[np][2], blo[np][3]);
                }
            }
        }

        // epilogue: +b2, relu, dot w3, reduce over tig, store
        float o[2][2] = {{0.f, 0.f}, {0.f, 0.f}};
        #pragma unroll
        for (int nt = 0; nt < 8; ++nt) {
            const int col = nt * 8 + 2 * tig;
            const float2 bb = *reinterpret_cast<const float2*>(sb2 + col);
            const float2 ww = *reinterpret_cast<const float2*>(sw3 + col);
            #pragma unroll
            for (int mt = 0; mt < 2; ++mt) {
                o[mt][0] = fmaf(fmaxf(acc[mt][nt][0] + bb.x, 0.f), ww.x, o[mt][0]);
                o[mt][0] = fmaf(fmaxf(acc[mt][nt][1] + bb.y, 0.f), ww.y, o[mt][0]);
                o[mt][1] = fmaf(fmaxf(acc[mt][nt][2] + bb.x, 0.f), ww.x, o[mt][1]);
                o[mt][1] = fmaf(fmaxf(acc[mt][nt][3] + bb.y, 0.f), ww.y, o[mt][1]);
            }
        }
        #pragma unroll
        for (int mt = 0; mt < 2; ++mt) {
            #pragma unroll
            for (int rh = 0; rh < 2; ++rh) {
                float v = o[mt][rh];
                v += __shfl_xor_sync(0xffffffffu, v, 1);
                v += __shfl_xor_sync(0xffffffffu, v, 2);
                if (tig == 0) {
                    const int orow = 32 * w + 16 * mt + 8 * rh + grp;
                    out[b * 128 + orow] = v + b3v;
                }
            }
        }
        ++it;
    }
}

// ---------------------------------------------------------------------------
extern "C" void kernel_launch(void* const* d_in, const int* in_sizes, int n_in,
                              void* d_out, int out_size) {
    const float* hidden  = (const float*)d_in[0];
    const float* actions = (const float*)d_in[1];
    const float* w1      = (const float*)d_in[2];
    const float* b1      = (const float*)d_in[3];
    const float* w2      = (const float*)d_in[4];
    const float* b2      = (const float*)d_in[5];
    const float* w3      = (const float*)d_in[6];
    const float* b3      = (const float*)d_in[7];
    float* out = (float*)d_out;

    cudaFuncSetAttribute(mma_kernel, cudaFuncAttributeMaxDynamicSharedMemorySize, SMEM_SZ);

    prep2_kernel<<<BB / 8, 256>>>(hidden, actions, w1, b1);
    mma_kernel<<<GRID_MMA, 128, SMEM_SZ>>>(w2, b2, w3, b3, out);
}

// round 15
// speedup vs baseline: 1.2144x; 1.2144x over previous
#include <cuda_runtime.h>
#include <cuda_bf16.h>
#include <cstdint>

// Problem constants
#define BB   2048
#define NAG  8
#define ACT  16
#define HIDN 64
#define GRID_MMA 444   // 3 CTAs per SM (148 SMs)
#define MAXT 5         // max tiles per CTA (2048 = 4*444 + 272)

// Scratch (__device__ globals: allowed)
__device__ float g_w1aT[HIDN * 128];   // w1aT[k*128 + row] = W1[(g*48+32+a)*64 + k]

// ---------------------------------------------------------------------------
__device__ __forceinline__ uint32_t pack_hi(float a, float b) {
    uint32_t r;
    asm("prmt.b32 %0, %1, %2, 0x7632;" : "=r"(r)
        : "r"(__float_as_uint(a)), "r"(__float_as_uint(b)));
    return r;
}
__device__ __forceinline__ uint32_t pack_lo(float a, float b) {
    float ha = __uint_as_float(__float_as_uint(a) & 0xffff0000u);
    float hb = __uint_as_float(__float_as_uint(b) & 0xffff0000u);
    float la = a - ha, lb = b - hb;
    uint32_t r;
    asm("cvt.rn.bf16x2.f32 %0, %1, %2;" : "=r"(r) : "f"(lb), "f"(la));
    return r;
}
__device__ __forceinline__ uint32_t smem_u32(const void* p) {
    uint32_t a;
    asm("{ .reg .u64 t; cvta.to.shared.u64 t, %1; cvt.u32.u64 %0, t; }" : "=r"(a) : "l"(p));
    return a;
}
__device__ __forceinline__ void fma4(float4& acc, float s, const float4 w) {
    acc.x = fmaf(s, w.x, acc.x);
    acc.y = fmaf(s, w.y, acc.y);
    acc.z = fmaf(s, w.z, acc.z);
    acc.w = fmaf(s, w.w, acc.w);
}

#define LDSM_X4(r, addr) \
    asm volatile("ldmatrix.sync.aligned.m8n8.x4.shared.b16 {%0,%1,%2,%3}, [%4];" \
        : "=r"((r)[0]), "=r"((r)[1]), "=r"((r)[2]), "=r"((r)[3]) : "r"(addr))
#define LDSM_X4_T(r, addr) \
    asm volatile("ldmatrix.sync.aligned.m8n8.x4.trans.shared.b16 {%0,%1,%2,%3}, [%4];" \
        : "=r"((r)[0]), "=r"((r)[1]), "=r"((r)[2]), "=r"((r)[3]) : "r"(addr))
#define MMA16816(c, a, b0, b1) \
    asm volatile("mma.sync.aligned.m16n8k16.row.col.f32.bf16.bf16.f32 " \
        "{%0,%1,%2,%3}, {%4,%5,%6,%7}, {%8,%9}, {%0,%1,%2,%3};" \
        : "+f"((c)[0]), "+f"((c)[1]), "+f"((c)[2]), "+f"((c)[3]) \
        : "r"((a)[0]), "r"((a)[1]), "r"((a)[2]), "r"((a)[3]), "r"(b0), "r"(b1))

// ---------------------------------------------------------------------------
// Tiny init: column-major action-row table g_w1aT[k*128 + row].
// ---------------------------------------------------------------------------
__global__ void __launch_bounds__(128) init_w1aT(const float* __restrict__ w1) {
    const int e   = blockIdx.x * 128 + threadIdx.x;
    const int k   = e >> 7;
    const int row = e & 127;
    const int g   = row >> 4;
    const int a   = row & 15;
    g_w1aT[e] = __ldg(w1 + (g * 48 + 32 + a) * 64 + k);
}

// ---------------------------------------------------------------------------
// Fused persistent kernel with hoisted prologue.
// PROLOGUE (once per CTA): stage hidden/actions for this CTA's <=5 batches,
// decode one-hot, batch-inner base dot over ONE pass of w1 (5x reuse/load),
// reduce to sbase_sm[5][64] (+b1 +sum_g w1row(g,idx_g)) and sidx_sm[5][8].
// MAIN LOOP (per tile, no gmem slabs): R14 structure verbatim —
//   build A': x1[row,k] = relu(sbase[k] + w1aT[k,row] - w1aT[k,rowsub]),
//   4 physical k-chunks x 3 bf16-split products, fused epilogue.
// ---------------------------------------------------------------------------
#define SM_A     0        // 32768 (A tile; prologue staging scratch)
#define SM_B     32768    // 16384: rows 0-63 = W_hi, 64-127 = W_lo
#define SM_B2    49152    // 256
#define SM_W3    49408    // 256
#define SM_SBASE 49664    // 1280: sbase_sm[5][64]
#define SM_SIDX  50944    // 192:  sidx_sm[5][8]
#define SMEM_SZ  51200
// prologue staging (inside SM_A region, dead after prologue):
#define ST_HID   0        // 5 x 1024 B
#define ST_ACT   8192     // 5 x 512 B
#define ST_PART  16384    // 5 x 8 x 16 float4 = 10240 B

__global__ void __launch_bounds__(128, 3) mma_kernel(
    const float* __restrict__ hidden,   // [B, 8, 32]
    const float* __restrict__ actions,  // [B, 8, 16]
    const float* __restrict__ w1,       // [384, 64]
    const float* __restrict__ b1,       // [64]
    const float* __restrict__ w2,       // [64, 64]
    const float* __restrict__ b2,       // [64]
    const float* __restrict__ w3,       // [64]
    const float* __restrict__ b3,       // [1]
    float* __restrict__ out)            // [B, 128]
{
    extern __shared__ __align__(16) char dsm[];
    const uint32_t smAddr = smem_u32(dsm);
    const uint32_t smA    = smAddr + SM_A;
    const uint32_t smB    = smAddr + SM_B;
    float*  sb2      = reinterpret_cast<float*>(dsm + SM_B2);
    float*  sw3      = reinterpret_cast<float*>(dsm + SM_W3);
    float4* sbase_sm = reinterpret_cast<float4*>(dsm + SM_SBASE);  // [5*16]
    int*    sidx_sm  = reinterpret_cast<int*>(dsm + SM_SIDX);      // [5*8]

    const int tid  = threadIdx.x;
    const int w    = tid >> 5;
    const int lane = tid & 31;
    const float4* __restrict__ w1v = reinterpret_cast<const float4*>(w1);

    const int nb = (blockIdx.x + 4 * GRID_MMA < BB) ? 5 : 4;   // tiles this CTA

    if (tid < 64) {
        sb2[tid] = __ldg(b2 + tid);
        sw3[tid] = __ldg(w3 + tid);
    }
    const float b3v = __ldg(b3);

    // ---- stage hidden + actions for nb batches (into A-region scratch) ----
    {
        const float4* hv = reinterpret_cast<const float4*>(hidden);
        float4* hst = reinterpret_cast<float4*>(dsm + ST_HID);
        for (int e = tid; e < nb * 64; e += 128) {
            const int j = e >> 6, q = e & 63;
            hst[e] = __ldg(hv + (size_t)(blockIdx.x + j * GRID_MMA) * 64 + q);
        }
        const float4* av = reinterpret_cast<const float4*>(actions);
        float4* ast = reinterpret_cast<float4*>(dsm + ST_ACT);
        for (int e = tid; e < nb * 32; e += 128) {
            const int j = e >> 5, q = e & 31;
            ast[e] = __ldg(av + (size_t)(blockIdx.x + j * GRID_MMA) * 32 + q);
        }
    }

    // ---- build B = [W_hi; W_lo] (128 k-rows x 64 n), xor-swizzled ----
    for (int e = tid; e < 128 * 32; e += 128) {
        const int kk = e >> 5;
        const int nw = e & 31;
        const int k  = kk & 63;
        const float2 f = __ldg(reinterpret_cast<const float2*>(w2 + k * 64 + 2 * nw));
        const uint32_t word = (kk < 64) ? pack_hi(f.x, f.y) : pack_lo(f.x, f.y);
        const int nc = nw >> 2;
        const uint32_t byte = (uint32_t)kk * 128u + (uint32_t)((nc ^ (kk & 7)) << 4)
                            + (uint32_t)((nw & 3) << 2);
        *reinterpret_cast<uint32_t*>(dsm + SM_B + byte) = word;
    }
    __syncthreads();

    // ---- one-hot decode (exact) ----
    if (tid < nb * 8) {
        const int j = tid >> 3, g = tid & 7;
        const float* ag = reinterpret_cast<const float*>(dsm + ST_ACT) + j * 128 + g * 16;
        float s = 0.f;
        #pragma unroll
        for (int a = 0; a < ACT; ++a) s = fmaf(ag[a], (float)a, s);
        sidx_sm[tid] = __float2int_rn(s);
    }

    // ---- base dot, batch-inner (w1 loaded once, nb-x reuse) ----
    {
        const int kq8 = tid >> 4;      // agent
        const int n4  = tid & 15;      // n-quad
        float4 accb[MAXT];
        #pragma unroll
        for (int j = 0; j < MAXT; ++j) accb[j] = make_float4(0.f, 0.f, 0.f, 0.f);
        const float* hsf = reinterpret_cast<const float*>(dsm + ST_HID);
        #pragma unroll 4
        for (int i = 0; i < 32; ++i) {
            const float4 w4 = __ldg(w1v + (kq8 * 48 + i) * 16 + n4);
            #pragma unroll
            for (int j = 0; j < MAXT; ++j)
                if (j < nb) fma4(accb[j], hsf[j * 256 + kq8 * 32 + i], w4);
        }
        float4* spart = reinterpret_cast<float4*>(dsm + ST_PART);
        #pragma unroll
        for (int j = 0; j < MAXT; ++j)
            if (j < nb) spart[(j * 8 + kq8) * 16 + n4] = accb[j];
    }
    __syncthreads();

    // ---- reduce to sbase: sum partials + b1 + sum_g w1row(g, idx_g) ----
    if (tid < nb * 16) {
        const int j  = tid >> 4;
        const int n4 = tid & 15;
        const float4* spart = reinterpret_cast<const float4*>(dsm + ST_PART);
        float4 s = spart[(j * 8) * 16 + n4];
        #pragma unroll
        for (int q = 1; q < 8; ++q) {
            const float4 p = spart[(j * 8 + q) * 16 + n4];
            s.x += p.x; s.y += p.y; s.z += p.z; s.w += p.w;
        }
        const float4 bv = __ldg(reinterpret_cast<const float4*>(b1) + n4);
        s.x += bv.x; s.y += bv.y; s.z += bv.z; s.w += bv.w;
        #pragma unroll
        for (int g = 0; g < NAG; ++g) {
            const float4 av = __ldg(w1v + (g * 48 + 32 + sidx_sm[j * 8 + g]) * 16 + n4);
            s.x += av.x; s.y += av.y; s.z += av.z; s.w += av.w;
        }
        sbase_sm[j * 16 + n4] = s;
    }
    __syncthreads();

    // ---- per-lane ldmatrix address precompute ----
    const int g2  = lane >> 4;
    const int gh  = (lane >> 3) & 1;
    const int lr  = lane & 7;
    const int grp = lane >> 2;
    const int tig = lane & 3;

    uint32_t aBase[2];
    #pragma unroll
    for (int mt = 0; mt < 2; ++mt)
        aBase[mt] = smA + (uint32_t)(32 * w + 16 * mt + 8 * gh + lr) * 256u;

    const int nadd = lane >> 4;
    const uint32_t bBase = smB + (uint32_t)(8 * ((lane >> 3) & 1) + lr) * 128u;
    uint32_t nxor[4];
    #pragma unroll
    for (int np = 0; np < 4; ++np)
        nxor[np] = (uint32_t)(((2 * np + nadd) ^ lr) << 4);

    const int row = tid;
    const int gq  = row >> 4;
    const uint32_t rbase = (uint32_t)row * 256u;
    const int rx  = row & 7;

    // ---- main loop: nb tiles, no gmem slab traffic ----
    for (int s = 0; s < nb; ++s) {
        const int b = blockIdx.x + s * GRID_MMA;
        const float4* sbase4 = sbase_sm + s * 16;
        const int rowsub = gq * 16 + sidx_sm[s * 8 + gq];

        // build A': x1[row,k] = relu(sbase[k] + w1aT[k,row] - w1aT[k,rowsub])
        #pragma unroll
        for (int c8 = 0; c8 < 8; ++c8) {
            const int k0 = c8 * 8;
            const float4 s0 = sbase4[c8 * 2];
            const float4 s1 = sbase4[c8 * 2 + 1];
            float x[8];
            x[0] = s0.x; x[1] = s0.y; x[2] = s0.z; x[3] = s0.w;
            x[4] = s1.x; x[5] = s1.y; x[6] = s1.z; x[7] = s1.w;
            #pragma unroll
            for (int j = 0; j < 8; ++j) {
                const int k = k0 + j;
                x[j] = fmaxf(x[j] + __ldg(g_w1aT + k * 128 + row)
                                  - __ldg(g_w1aT + k * 128 + rowsub), 0.f);
            }

            uint4 hi4, lo4;
            hi4.x = pack_hi(x[0], x[1]); hi4.y = pack_hi(x[2], x[3]);
            hi4.z = pack_hi(x[4], x[5]); hi4.w = pack_hi(x[6], x[7]);
            lo4.x = pack_lo(x[0], x[1]); lo4.y = pack_lo(x[2], x[3]);
            lo4.z = pack_lo(x[4], x[5]); lo4.w = pack_lo(x[6], x[7]);

            *reinterpret_cast<uint4*>(dsm + SM_A + rbase + ((c8 ^ rx) << 4))       = hi4;
            *reinterpret_cast<uint4*>(dsm + SM_A + rbase + (((8 + c8) ^ rx) << 4)) = lo4;
        }
        __syncthreads();

        // mma phase: 4 physical k-chunks x 3 split products
        float acc[2][8][4];
        #pragma unroll
        for (int mt = 0; mt < 2; ++mt)
            #pragma unroll
            for (int nt = 0; nt < 8; ++nt)
                #pragma unroll
                for (int q = 0; q < 4; ++q) acc[mt][nt][q] = 0.f;

        #pragma unroll
        for (int kp = 0; kp < 4; ++kp) {
            uint32_t ah[2][4], al[2][4];
            #pragma unroll
            for (int mt = 0; mt < 2; ++mt) {
                LDSM_X4(ah[mt], aBase[mt] + (uint32_t)(((2 * kp + g2) ^ lr) << 4));
                LDSM_X4(al[mt], aBase[mt] + (uint32_t)(((8 + 2 * kp + g2) ^ lr) << 4));
            }
            uint32_t bh[4][4], blo[4][4];
            #pragma unroll
            for (int np = 0; np < 4; ++np) {
                LDSM_X4_T(bh[np],  bBase + (uint32_t)(kp * 2048)       + nxor[np]);
                LDSM_X4_T(blo[np], bBase + (uint32_t)((4 + kp) * 2048) + nxor[np]);
            }
            #pragma unroll
            for (int mt = 0; mt < 2; ++mt) {
                #pragma unroll
                for (int np = 0; np < 4; ++np) {
                    MMA16816(acc[mt][2 * np + 0], ah[mt], bh[np][0],  bh[np][1]);
                    MMA16816(acc[mt][2 * np + 1], ah[mt], bh[np][2],  bh[np][3]);
                    MMA16816(acc[mt][2 * np + 0], al[mt], bh[np][0],  bh[np][1]);
                    MMA16816(acc[mt][2 * np + 1], al[mt], bh[np][2],  bh[np][3]);
                    MMA16816(acc[mt][2 * np + 0], ah[mt], blo[np][0], blo[np][1]);
                    MMA16816(acc[mt][2 * np + 1], ah[mt], blo[np][2], blo[np][3]);
                }
            }
        }

        // epilogue: +b2, relu, dot w3, reduce over tig, store
        float o[2][2] = {{0.f, 0.f}, {0.f, 0.f}};
        #pragma unroll
        for (int nt = 0; nt < 8; ++nt) {
            const int col = nt * 8 + 2 * tig;
            const float2 bb = *reinterpret_cast<const float2*>(sb2 + col);
            const float2 ww = *reinterpret_cast<const float2*>(sw3 + col);
            #pragma unroll
            for (int mt = 0; mt < 2; ++mt) {
                o[mt][0] = fmaf(fmaxf(acc[mt][nt][0] + bb.x, 0.f), ww.x, o[mt][0]);
                o[mt][0] = fmaf(fmaxf(acc[mt][nt][1] + bb.y, 0.f), ww.y, o[mt][0]);
                o[mt][1] = fmaf(fmaxf(acc[mt][nt][2] + bb.x, 0.f), ww.x, o[mt][1]);
                o[mt][1] = fmaf(fmaxf(acc[mt][nt][3] + bb.y, 0.f), ww.y, o[mt][1]);
            }
        }
        #pragma unroll
        for (int mt = 0; mt < 2; ++mt) {
            #pragma unroll
            for (int rh = 0; rh < 2; ++rh) {
                float v = o[mt][rh];
                v += __shfl_xor_sync(0xffffffffu, v, 1);
                v += __shfl_xor_sync(0xffffffffu, v, 2);
                if (tig == 0) {
                    const int orow = 32 * w + 16 * mt + 8 * rh + grp;
                    out[b * 128 + orow] = v + b3v;
                }
            }
        }
        __syncthreads();   // protect A before next build
    }
}

// ---------------------------------------------------------------------------
extern "C" void kernel_launch(void* const* d_in, const int* in_sizes, int n_in,
                              void* d_out, int out_size) {
    const float* hidden  = (const float*)d_in[0];
    const float* actions = (const float*)d_in[1];
    const float* w1      = (const float*)d_in[2];
    const float* b1      = (const float*)d_in[3];
    const float* w2      = (const float*)d_in[4];
    const float* b2      = (const float*)d_in[5];
    const float* w3      = (const float*)d_in[6];
    const float* b3      = (const float*)d_in[7];
    float* out = (float*)d_out;

    cudaFuncSetAttribute(mma_kernel, cudaFuncAttributeMaxDynamicSharedMemorySize, SMEM_SZ);

    init_w1aT<<<64, 128>>>(w1);
    mma_kernel<<<GRID_MMA, 128, SMEM_SZ>>>(hidden, actions, w1, b1,
                                           w2, b2, w3, b3, out);
}